// round 4
// baseline (speedup 1.0000x reference)
#include <cuda_runtime.h>

// CoupledClustersLossV2 — single-pass HBM-bound reduction.
// embeddings: [256 classes][2 (pos/neg)][32 samples][2048] fp32, 128 MB.
// Per class: anchor = mean(pos); ap_i = ||pos_i - anchor||;
//            an = sqrt(min_i ||neg_i - anchor||^2);
//            loss_c = sum_i relu(ap_i - an + 0.3)^2 ; out = mean_c loss_c.
// Algebraic expansion with s = sum_j pos_j:
//   ||x - a||^2 = ||x||^2 - (x·s)/16 + ||s||^2/1024
// decomposes over D-chunks -> exactly one pass over global memory.

#define NCLS    256
#define NS      32
#define DIM     2048
#define CHUNK   128
#define NCHUNK  (DIM / CHUNK)            // 16
#define THREADS 256
#define F4ROW   (CHUNK / 4)              // 32 float4 per chunk-row
#define LPT     (NS * F4ROW / THREADS)   // 4 float4 loads / thread / tile
#define MARGIN  0.3f

__device__ float g_class_loss[NCLS];

__global__ __launch_bounds__(THREADS, 2)
void ccl_class_kernel(const float* __restrict__ emb)
{
    __shared__ float Apos[NS][CHUNK];        // 16 KB
    __shared__ float Aneg[NS][CHUNK];        // 16 KB
    __shared__ float s_sh[CHUNK];            // column sums of pos chunk
    __shared__ float red_pn[NS], red_tp[NS], red_nn[NS], red_tn[NS];

    const int cls  = blockIdx.x;
    const int tid  = threadIdx.x;
    const int warp = tid >> 5;
    const int lane = tid & 31;

    const float* base = emb + (size_t)cls * (size_t)(2 * NS * DIM);

    // Per-thread fixed (row, col4) mapping for tile loads.
    int lrow[LPT], lcol[LPT];
#pragma unroll
    for (int it = 0; it < LPT; ++it) {
        int idx = tid + it * THREADS;
        lrow[it] = idx >> 5;   // idx / F4ROW
        lcol[it] = idx & 31;   // idx % F4ROW
    }

    // Global float4 pointers for pos / neg rows (advance by CHUNK/4 per tile).
    const float4* pptr[LPT];
    const float4* nptr[LPT];
#pragma unroll
    for (int it = 0; it < LPT; ++it) {
        pptr[it] = (const float4*)(base + (size_t)lrow[it] * DIM) + lcol[it];
        nptr[it] = (const float4*)(base + (size_t)(NS + lrow[it]) * DIM) + lcol[it];
    }

    // Accumulators: warp w owns rows 4w..4w+3 (pos and neg); lane owns 4 cols/chunk.
    float pn[4] = {0.f,0.f,0.f,0.f};   // ||pos||^2 partials
    float tp[4] = {0.f,0.f,0.f,0.f};   // pos·s     partials
    float nn[4] = {0.f,0.f,0.f,0.f};   // ||neg||^2 partials
    float tn[4] = {0.f,0.f,0.f,0.f};   // neg·s     partials

    // Prefetch tile 0 into registers.
    float4 pbuf[LPT], nbuf[LPT];
#pragma unroll
    for (int it = 0; it < LPT; ++it) {
        pbuf[it] = pptr[it][0];
        nbuf[it] = nptr[it][0];
        pptr[it] += F4ROW;
        nptr[it] += F4ROW;
    }

    for (int k = 0; k < NCHUNK; ++k) {
        // Stage current tile into SMEM.
#pragma unroll
        for (int it = 0; it < LPT; ++it) {
            *(float4*)&Apos[lrow[it]][lcol[it] * 4] = pbuf[it];
            *(float4*)&Aneg[lrow[it]][lcol[it] * 4] = nbuf[it];
        }
        __syncthreads();

        // Prefetch next tile (LDGs in flight while we compute below).
        if (k + 1 < NCHUNK) {
#pragma unroll
            for (int it = 0; it < LPT; ++it) {
                pbuf[it] = pptr[it][0];
                nbuf[it] = nptr[it][0];
                pptr[it] += F4ROW;
                nptr[it] += F4ROW;
            }
        }

        // Column sums of the pos chunk: s_chunk[c] = sum_i pos_i[c].
        if (tid < CHUNK) {
            float s = 0.f;
#pragma unroll
            for (int i = 0; i < NS; ++i) s += Apos[i][tid];
            s_sh[tid] = s;
        }
        __syncthreads();

        // Accumulate norms and dot-with-s. float4 LDS, conflict-free.
        float4 sc = *(const float4*)&s_sh[lane * 4];
#pragma unroll
        for (int r = 0; r < 4; ++r) {
            const int row = warp * 4 + r;
            float4 x = *(const float4*)&Apos[row][lane * 4];
            pn[r] = fmaf(x.x, x.x, fmaf(x.y, x.y, fmaf(x.z, x.z, fmaf(x.w, x.w, pn[r]))));
            tp[r] = fmaf(x.x, sc.x, fmaf(x.y, sc.y, fmaf(x.z, sc.z, fmaf(x.w, sc.w, tp[r]))));
            float4 y = *(const float4*)&Aneg[row][lane * 4];
            nn[r] = fmaf(y.x, y.x, fmaf(y.y, y.y, fmaf(y.z, y.z, fmaf(y.w, y.w, nn[r]))));
            tn[r] = fmaf(y.x, sc.x, fmaf(y.y, sc.y, fmaf(y.z, sc.z, fmaf(y.w, sc.w, tn[r]))));
        }
        __syncthreads();   // protect tile before next store
    }

    // Lane-reduce each per-row accumulator across the warp (fixed order: deterministic).
#pragma unroll
    for (int r = 0; r < 4; ++r) {
#pragma unroll
        for (int off = 16; off > 0; off >>= 1) {
            pn[r] += __shfl_xor_sync(0xffffffffu, pn[r], off);
            tp[r] += __shfl_xor_sync(0xffffffffu, tp[r], off);
            nn[r] += __shfl_xor_sync(0xffffffffu, nn[r], off);
            tn[r] += __shfl_xor_sync(0xffffffffu, tn[r], off);
        }
        if (lane == 0) {
            red_pn[warp * 4 + r] = pn[r];
            red_tp[warp * 4 + r] = tp[r];
            red_nn[warp * 4 + r] = nn[r];
            red_tn[warp * 4 + r] = tn[r];
        }
    }
    __syncthreads();

    // Final per-class math: warp 0, lane i handles sample row i.
    if (warp == 0) {
        float pnv = red_pn[lane];
        float tpv = red_tp[lane];
        float nnv = red_nn[lane];
        float tnv = red_tn[lane];

        // ||s||^2 = sum_i (pos_i · s)
        float ssum = tpv;
#pragma unroll
        for (int off = 16; off > 0; off >>= 1)
            ssum += __shfl_xor_sync(0xffffffffu, ssum, off);
        const float anorm = ssum * (1.0f / 1024.0f);   // ||a||^2 = ||s||^2 / 32^2

        float ap2 = pnv - tpv * (1.0f / 16.0f) + anorm;  // -2*(x·s)/32
        float nd2 = nnv - tnv * (1.0f / 16.0f) + anorm;

        float mn = nd2;
#pragma unroll
        for (int off = 16; off > 0; off >>= 1)
            mn = fminf(mn, __shfl_xor_sync(0xffffffffu, mn, off));
        const float an = sqrtf(fmaxf(mn, 0.0f));

        float t = sqrtf(fmaxf(ap2, 0.0f)) - an + MARGIN;
        t = fmaxf(t, 0.0f);
        float term = t * t;
#pragma unroll
        for (int off = 16; off > 0; off >>= 1)
            term += __shfl_xor_sync(0xffffffffu, term, off);

        if (lane == 0) g_class_loss[cls] = term;
    }
}

// Deterministic fixed-order final mean over the 256 class losses.
__global__ void ccl_reduce_kernel(float* __restrict__ out)
{
    __shared__ float sm[8];
    const int tid = threadIdx.x;
    float v = g_class_loss[tid];
#pragma unroll
    for (int off = 16; off > 0; off >>= 1)
        v += __shfl_xor_sync(0xffffffffu, v, off);
    if ((tid & 31) == 0) sm[tid >> 5] = v;
    __syncthreads();
    if (tid == 0) {
        float t = 0.f;
#pragma unroll
        for (int i = 0; i < 8; ++i) t += sm[i];
        out[0] = t * (1.0f / (float)NCLS);
    }
}

extern "C" void kernel_launch(void* const* d_in, const int* in_sizes, int n_in,
                              void* d_out, int out_size)
{
    (void)in_sizes; (void)n_in; (void)out_size;
    const float* emb = (const float*)d_in[0];   // embeddings [16384, 2048] fp32
    // target (d_in[1]) is unused by the reference computation.
    ccl_class_kernel<<<NCLS, THREADS>>>(emb);
    ccl_reduce_kernel<<<1, NCLS>>>((float*)d_out);
}